// round 16
// baseline (speedup 1.0000x reference)
#include <cuda_runtime.h>
#include <cuda_fp16.h>
#include <math.h>
#include <stdint.h>

#define Bsz 128
#define D 100
#define D2 10000
#define M_ROWS 12800      // B*D
#define M_PAD 12864       // 134 * 96
#define MTILE 96
#define KP 128            // padded K (storage in gmem scratch)
#define K_STEPS 7         // 7*16 = 112 >= 100
#define NTILE 64
#define NBLK 13           // i padded to 104 -> 13 blocks of 8
#define NPAIRS 91         // 13*14/2
#define N_SYM (NPAIRS * 64)   // 5824 packed hess columns
#define NJ_PAD 128        // 2 jac n-tiles
#define THREADS 128

// ---------------- scratch (device globals) ----------------
__device__ __half g_AJh[M_PAD * KP];                 // fp16 A (jac)
__device__ __half g_AHh[M_PAD * KP];                 // fp16 A (hess)
__device__ __half g_PBh[(size_t)N_SYM * KP];         // packed sym P (fp16)
__device__ __half g_BJh[NJ_PAD * KP];                // W1t (fp16)

// ---------------- helpers ----------------
__device__ __forceinline__ uint32_t smem_to_u32(const void* p) {
    uint32_t a;
    asm("{ .reg .u64 t; cvta.to.shared.u64 t, %1; cvt.u32.u64 %0, t; }" : "=r"(a) : "l"(p));
    return a;
}
__device__ __forceinline__ void ldm4(uint32_t r[4], uint32_t addr) {
    asm volatile("ldmatrix.sync.aligned.m8n8.x4.shared.b16 {%0,%1,%2,%3}, [%4];"
                 : "=r"(r[0]), "=r"(r[1]), "=r"(r[2]), "=r"(r[3]) : "r"(addr));
}
__device__ __forceinline__ void mma_f16(float c[4], const uint32_t a[4],
                                        uint32_t b0, uint32_t b1) {
    asm volatile(
        "mma.sync.aligned.m16n8k16.row.col.f32.f16.f16.f32 "
        "{%0,%1,%2,%3}, {%4,%5,%6,%7}, {%8,%9}, {%0,%1,%2,%3};"
        : "+f"(c[0]), "+f"(c[1]), "+f"(c[2]), "+f"(c[3])
        : "r"(a[0]), "r"(a[1]), "r"(a[2]), "r"(a[3]), "r"(b0), "r"(b1));
}
__device__ __forceinline__ void cp16(uint32_t dst, const void* src) {
    asm volatile("cp.async.cg.shared.global [%0], [%1], 16;" :: "r"(dst), "l"(src) : "memory");
}
__device__ __forceinline__ void decode_pair(int t, int& bi, int& bj) {
    int b = 0, rem = t;
    while (rem >= NBLK - b) { rem -= NBLK - b; b++; }
    bi = b; bj = b + rem;
}

// ---------------- fused prep: GELU derivs + out row + A rows for one batch b ----------------
// grid: Bsz+1 blocks of 128. Block Bsz zeroes the padded A rows [12800, 12864).
__global__ void fused_prep_kernel(const float* __restrict__ x,
                                  const float* __restrict__ W1,
                                  const float* __restrict__ b1,
                                  const float* __restrict__ W2,
                                  const float* __restrict__ b2,
                                  float* __restrict__ out) {
    int b = blockIdx.x;
    int t = threadIdx.x;

    if (b == Bsz) {
        for (int m = M_ROWS; m < M_PAD; m++) {
            g_AJh[m * KP + t] = __float2half_rn(0.0f);
            g_AHh[m * KP + t] = __float2half_rn(0.0f);
        }
        return;
    }

    __shared__ float xs[D];
    __shared__ float G0s[D], G1s[D], G2s[D];
    if (t < D) xs[t] = x[b * D + t];
    __syncthreads();
    if (t < D) {
        const float* w = W1 + t * D;
        float z = b1[t];
        #pragma unroll 4
        for (int i = 0; i < D; i++) z = fmaf(w[i], xs[i], z);
        float cdf = 0.5f * (1.0f + erff(z * 0.70710678118654752f));
        float pdf = 0.39894228040143268f * expf(-0.5f * z * z);
        G0s[t] = z * cdf;
        G1s[t] = cdf + z * pdf;
        G2s[t] = (2.0f - z * z) * pdf;
    }
    __syncthreads();

    if (t < D) {
        const float* w = W2 + t * D;
        float acc = b2[t];
        #pragma unroll 4
        for (int k = 0; k < D; k++) acc = fmaf(w[k], G0s[k], acc);
        out[b * D + t] = acc;
    }

    float g1 = (t < D) ? G1s[t] : 0.0f;
    float g2 = (t < D) ? G2s[t] : 0.0f;
    for (int o = 0; o < D; o++) {
        float w = (t < D) ? W2[o * D + t] : 0.0f;
        size_t m = (size_t)(b * D + o) * KP + t;
        g_AJh[m] = __float2half_rn(w * g1);
        g_AHh[m] = __float2half_rn(w * g2);
    }
}

// ---------------- packed symmetric P + BJ (fp16, one launch) ----------------
__global__ void buildPBJ_kernel(const float* __restrict__ W1) {
    int n = blockIdx.x;   // 0..N_SYM+NJ_PAD-1
    int k = threadIdx.x;  // 128
    if (n < N_SYM) {
        int t = n >> 6, nl = n & 63;
        int bi, bj; decode_pair(t, bi, bj);
        int i = bi * 8 + (nl >> 3);
        int j = bj * 8 + (nl & 7);
        float v = 0.0f;
        if (i < D && j < D && k < D)
            v = __ldg(W1 + k * D + i) * __ldg(W1 + k * D + j);
        g_PBh[(size_t)n * KP + k] = __float2half_rn(v);
    } else {
        int nn = n - N_SYM;     // 0..127
        float v = (nn < D && k < D) ? W1[k * D + nn] : 0.0f;
        g_BJh[nn * KP + k] = __float2half_rn(v);
    }
}

// ---------------- HMMA GEMM: A-resident dual-B-tile CTA ----------------
// grid.x = 47: bx<45 -> hess tiles {2bx, 2bx+1}; bx==45 -> hess tile 90;
//              bx==46 -> jac tiles {n0=0, n0=64}
#define PITCH 240                          // bytes per smem row (112 fp16 + pad)
#define CHUNKS 14
#define A_TILE_BYTES (MTILE * PITCH)       // 23040
#define B_TILE_BYTES (NTILE * PITCH)       // 15360
#define SMEM_BYTES (A_TILE_BYTES + 2 * B_TILE_BYTES)  // 53760 -> 4 CTAs/SM
#define CPITCH 68                          // half-tile C staging pitch (floats): 48*68*4 = 13056

template <int ROWS>
__device__ __forceinline__ void load_tile_async(uint32_t dst, const __half* __restrict__ src,
                                                int row0, int tid) {
    constexpr int TOT = ROWS * CHUNKS;
    #pragma unroll
    for (int it = 0; it < (TOT + THREADS - 1) / THREADS; it++) {
        int c = tid + it * THREADS;
        if (TOT % THREADS != 0 && c >= TOT) break;
        int row = c / CHUNKS, col = c % CHUNKS;
        cp16(dst + row * PITCH + col * 16,
             src + (size_t)(row0 + row) * KP + col * 8);
    }
}

__global__ void __launch_bounds__(THREADS, 4)
mma_gemm_kernel(float* __restrict__ Chess, float* __restrict__ Cjac) {
    int bx = blockIdx.x;
    bool is_jac = (bx == 46);
    int nt = (bx == 45) ? 1 : 2;

    const __half* __restrict__ A = is_jac ? g_AJh : g_AHh;
    const __half* __restrict__ B = is_jac ? g_BJh : g_PBh;

    extern __shared__ char smem[];
    uint32_t uA  = smem_to_u32(smem);
    uint32_t uB0 = uA + A_TILE_BYTES;
    uint32_t uB1 = uB0 + B_TILE_BYTES;
    float* Cs = reinterpret_cast<float*>(smem + A_TILE_BYTES);  // overlays B0 (epilogue only)

    int tid = threadIdx.x;
    int m0 = blockIdx.y * MTILE;

    int n00 = is_jac ? 0  : (bx * 2) * NTILE;
    int n01 = is_jac ? 64 : (bx * 2 + 1) * NTILE;

    load_tile_async<MTILE>(uA, A, m0, tid);
    load_tile_async<NTILE>(uB0, B, n00, tid);
    asm volatile("cp.async.commit_group;" ::: "memory");
    if (nt == 2) {
        load_tile_async<NTILE>(uB1, B, n01, tid);
        asm volatile("cp.async.commit_group;" ::: "memory");
        asm volatile("cp.async.wait_group 1;" ::: "memory");
    } else {
        asm volatile("cp.async.wait_group 0;" ::: "memory");
    }
    __syncthreads();

    int lane = tid & 31, wid = tid >> 5;
    int wm = (wid & 1) * 48;      // 2 m-warps x 48
    int wn = (wid >> 1) * 32;     // 2 n-warps x 32
    int t = lane >> 3, r = lane & 7;

    uint32_t aoff = (uint32_t)((wm + (t & 1) * 8 + r) * PITCH + (t >> 1) * 16);
    uint32_t boff = (uint32_t)((wn + (t >> 1) * 8 + r) * PITCH + (t & 1) * 16);

    for (int s = 0; s < nt; s++) {
        if (s == 1) {
            asm volatile("cp.async.wait_group 0;" ::: "memory");
            __syncthreads();     // B1 visible; also Cs(B0) reads from epi0 done
        }
        uint32_t uB = s ? uB1 : uB0;
        int n0 = s ? n01 : n00;

        float acc[3][4][4];
        #pragma unroll
        for (int i = 0; i < 3; i++)
            #pragma unroll
            for (int j = 0; j < 4; j++)
                #pragma unroll
                for (int e = 0; e < 4; e++) acc[i][j][e] = 0.0f;

        #pragma unroll
        for (int ks = 0; ks < K_STEPS; ks++) {
            uint32_t kb = ks * 32;
            uint32_t ah[3][4], bh[8];
            #pragma unroll
            for (int mf = 0; mf < 3; mf++) ldm4(ah[mf], uA + aoff + mf * 16 * PITCH + kb);
            ldm4(bh,     uB + boff + kb);
            ldm4(bh + 4, uB + boff + 16 * PITCH + kb);
            #pragma unroll
            for (int mf = 0; mf < 3; mf++)
                #pragma unroll
                for (int nf = 0; nf < 4; nf++)
                    mma_f16(acc[mf][nf], ah[mf], bh[nf * 2], bh[nf * 2 + 1]);
        }

        int bi = 0, bj = 0;
        if (!is_jac) decode_pair(bx * 2 + s, bi, bj);
        bool fast = !is_jac && bi < 12 && bj < 12;

        // epilogue in two 48-row half phases staged over B0's region
        #pragma unroll
        for (int h = 0; h < 2; h++) {
            __syncthreads();   // mainloop reads of B0 done (h=0,s=0); prior phase reads done
            if (wm == h * 48) {
                #pragma unroll
                for (int mf = 0; mf < 3; mf++) {
                    int mrow = mf * 16 + (lane >> 2);   // local 0..47 (+8)
                    #pragma unroll
                    for (int nf = 0; nf < 4; nf++) {
                        int ncol = wn + nf * 8 + 2 * (lane & 3);
                        *reinterpret_cast<float2*>(&Cs[mrow * CPITCH + ncol]) =
                            make_float2(acc[mf][nf][0], acc[mf][nf][1]);
                        *reinterpret_cast<float2*>(&Cs[(mrow + 8) * CPITCH + ncol]) =
                            make_float2(acc[mf][nf][2], acc[mf][nf][3]);
                    }
                }
            }
            __syncthreads();

            int gmb = m0 + h * 48;
            if (is_jac) {
                #pragma unroll
                for (int it = 0; it < 48 * 64 / THREADS; it++) {
                    int e = tid + it * THREADS;
                    int m = e >> 6, nl = e & 63;
                    int n = n0 + nl;
                    int gm = gmb + m;
                    if (n < D && gm < M_ROWS) Cjac[(size_t)gm * D + n] = Cs[m * CPITCH + nl];
                }
            } else if (fast) {
                #pragma unroll
                for (int it = 0; it < 48 * 16 / THREADS; it++) {
                    int e = tid + it * THREADS;
                    int m = e >> 4, q = e & 15;
                    int gm = gmb + m;
                    if (gm >= M_ROWS) continue;
                    int i = bi * 8 + (q >> 1);
                    int jb = bj * 8 + (q & 1) * 4;
                    float4 v = *reinterpret_cast<const float4*>(&Cs[m * CPITCH + q * 4]);
                    *reinterpret_cast<float4*>(&Chess[(size_t)gm * D2 + i * D + jb]) = v;
                }
                #pragma unroll
                for (int it = 0; it < 48 * 16 / THREADS; it++) {
                    int e = tid + it * THREADS;
                    int m = e >> 4, q = e & 15;
                    int gm = gmb + m;
                    if (gm >= M_ROWS) continue;
                    int lj = q >> 1, li4 = (q & 1) * 4;
                    int jrow = bj * 8 + lj;
                    int ib = bi * 8 + li4;
                    float4 v;
                    v.x = Cs[m * CPITCH + (li4 + 0) * 8 + lj];
                    v.y = Cs[m * CPITCH + (li4 + 1) * 8 + lj];
                    v.z = Cs[m * CPITCH + (li4 + 2) * 8 + lj];
                    v.w = Cs[m * CPITCH + (li4 + 3) * 8 + lj];
                    *reinterpret_cast<float4*>(&Chess[(size_t)gm * D2 + jrow * D + ib]) = v;
                }
            } else {
                #pragma unroll
                for (int it = 0; it < 48 * 64 / THREADS; it++) {
                    int e = tid + it * THREADS;
                    int m = e >> 6, nl = e & 63;
                    int gm = gmb + m;
                    int i = bi * 8 + (nl >> 3), j = bj * 8 + (nl & 7);
                    if (i < D && j < D && gm < M_ROWS)
                        Chess[(size_t)gm * D2 + i * D + j] = Cs[m * CPITCH + nl];
                }
                #pragma unroll
                for (int it = 0; it < 48 * 64 / THREADS; it++) {
                    int e = tid + it * THREADS;
                    int m = e >> 6, nl = e & 63;
                    int gm = gmb + m;
                    int lj = nl >> 3, li = nl & 7;
                    int i = bi * 8 + li, j = bj * 8 + lj;
                    if (i < D && j < D && gm < M_ROWS)
                        Chess[(size_t)gm * D2 + j * D + i] = Cs[m * CPITCH + li * 8 + lj];
                }
            }
        }
        __syncthreads();   // all Cs reads done before next tile stages
    }
}

// ---------------- host ----------------
extern "C" void kernel_launch(void* const* d_in, const int* in_sizes, int n_in,
                              void* d_out, int out_size) {
    const float* x  = (const float*)d_in[0];
    const float* W1 = (const float*)d_in[1];
    const float* b1 = (const float*)d_in[2];
    const float* W2 = (const float*)d_in[3];
    const float* b2 = (const float*)d_in[4];

    float* out  = (float*)d_out;
    float* jac  = out + Bsz * D;
    float* hess = jac + (size_t)Bsz * D * D;

    cudaFuncSetAttribute(mma_gemm_kernel, cudaFuncAttributeMaxDynamicSharedMemorySize, SMEM_BYTES);

    buildPBJ_kernel<<<N_SYM + NJ_PAD, 128>>>(W1);                          // 0
    fused_prep_kernel<<<Bsz + 1, 128>>>(x, W1, b1, W2, b2, out);           // 1
    {
        dim3 grid(47, M_PAD / MTILE);
        mma_gemm_kernel<<<grid, THREADS, SMEM_BYTES>>>(hess, jac);         // 2
    }
}

// round 17
// speedup vs baseline: 1.2666x; 1.2666x over previous
#include <cuda_runtime.h>
#include <cuda_fp16.h>
#include <math.h>
#include <stdint.h>

#define Bsz 128
#define D 100
#define D2 10000
#define M_ROWS 12800      // B*D
#define M_PAD 12864       // 134 * 96
#define MTILE 96
#define KP 128            // padded K (storage in gmem scratch)
#define K_STEPS 7         // 7*16 = 112 >= 100
#define NTILE 64
#define NBLK 13           // i padded to 104 -> 13 blocks of 8
#define NPAIRS 91         // 13*14/2
#define N_SYM (NPAIRS * 64)   // 5824 packed hess columns
#define NJ_PAD 128        // 2 jac n-tiles
#define THREADS 128

// ---------------- scratch (device globals) ----------------
__device__ __half g_AJh[M_PAD * KP];                 // fp16 A (jac)
__device__ __half g_AHh[M_PAD * KP];                 // fp16 A (hess)
__device__ __half g_PBh[(size_t)N_SYM * KP];         // packed sym P, high
__device__ __half g_PBl[(size_t)N_SYM * KP];         // packed sym P, low
__device__ __half g_BJh[NJ_PAD * KP];                // W1t, high
__device__ __half g_BJl[NJ_PAD * KP];                // W1t, low

// ---------------- helpers ----------------
__device__ __forceinline__ uint32_t smem_to_u32(const void* p) {
    uint32_t a;
    asm("{ .reg .u64 t; cvta.to.shared.u64 t, %1; cvt.u32.u64 %0, t; }" : "=r"(a) : "l"(p));
    return a;
}
__device__ __forceinline__ void split_f16(float v, __half& h, __half& l) {
    h = __float2half_rn(v);
    l = __float2half_rn(v - __half2float(h));
}
__device__ __forceinline__ void ldm4(uint32_t r[4], uint32_t addr) {
    asm volatile("ldmatrix.sync.aligned.m8n8.x4.shared.b16 {%0,%1,%2,%3}, [%4];"
                 : "=r"(r[0]), "=r"(r[1]), "=r"(r[2]), "=r"(r[3]) : "r"(addr));
}
__device__ __forceinline__ void mma_f16(float c[4], const uint32_t a[4],
                                        uint32_t b0, uint32_t b1) {
    asm volatile(
        "mma.sync.aligned.m16n8k16.row.col.f32.f16.f16.f32 "
        "{%0,%1,%2,%3}, {%4,%5,%6,%7}, {%8,%9}, {%0,%1,%2,%3};"
        : "+f"(c[0]), "+f"(c[1]), "+f"(c[2]), "+f"(c[3])
        : "r"(a[0]), "r"(a[1]), "r"(a[2]), "r"(a[3]), "r"(b0), "r"(b1));
}
__device__ __forceinline__ void cp16(uint32_t dst, const void* src) {
    asm volatile("cp.async.cg.shared.global [%0], [%1], 16;" :: "r"(dst), "l"(src) : "memory");
}
__device__ __forceinline__ void decode_pair(int t, int& bi, int& bj) {
    int b = 0, rem = t;
    while (rem >= NBLK - b) { rem -= NBLK - b; b++; }
    bi = b; bj = b + rem;
}

// ---------------- fused prep: GELU derivs + out row + A rows for one batch b ----------------
// grid: Bsz+1 blocks of 128. Block Bsz zeroes the padded A rows [12800, 12864).
__global__ void fused_prep_kernel(const float* __restrict__ x,
                                  const float* __restrict__ W1,
                                  const float* __restrict__ b1,
                                  const float* __restrict__ W2,
                                  const float* __restrict__ b2,
                                  float* __restrict__ out) {
    int b = blockIdx.x;
    int t = threadIdx.x;

    if (b == Bsz) {
        for (int m = M_ROWS; m < M_PAD; m++) {
            g_AJh[m * KP + t] = __float2half_rn(0.0f);
            g_AHh[m * KP + t] = __float2half_rn(0.0f);
        }
        return;
    }

    __shared__ float xs[D];
    __shared__ float G0s[D], G1s[D], G2s[D];
    if (t < D) xs[t] = x[b * D + t];
    __syncthreads();
    if (t < D) {
        const float* w = W1 + t * D;
        float z = b1[t];
        #pragma unroll 4
        for (int i = 0; i < D; i++) z = fmaf(w[i], xs[i], z);
        float cdf = 0.5f * (1.0f + erff(z * 0.70710678118654752f));
        float pdf = 0.39894228040143268f * expf(-0.5f * z * z);
        G0s[t] = z * cdf;
        G1s[t] = cdf + z * pdf;
        G2s[t] = (2.0f - z * z) * pdf;
    }
    __syncthreads();

    if (t < D) {
        const float* w = W2 + t * D;
        float acc = b2[t];
        #pragma unroll 4
        for (int k = 0; k < D; k++) acc = fmaf(w[k], G0s[k], acc);
        out[b * D + t] = acc;
    }

    float g1 = (t < D) ? G1s[t] : 0.0f;
    float g2 = (t < D) ? G2s[t] : 0.0f;
    for (int o = 0; o < D; o++) {
        float w = (t < D) ? W2[o * D + t] : 0.0f;
        size_t m = (size_t)(b * D + o) * KP + t;
        g_AJh[m] = __float2half_rn(w * g1);
        g_AHh[m] = __float2half_rn(w * g2);
    }
}

// ---------------- packed symmetric P + BJ, fp16 split (one launch) ----------------
__global__ void buildPBJ_kernel(const float* __restrict__ W1) {
    int n = blockIdx.x;   // 0..N_SYM+NJ_PAD-1
    int k = threadIdx.x;  // 128
    if (n < N_SYM) {
        int t = n >> 6, nl = n & 63;
        int bi, bj; decode_pair(t, bi, bj);
        int i = bi * 8 + (nl >> 3);
        int j = bj * 8 + (nl & 7);
        float v = 0.0f;
        if (i < D && j < D && k < D)
            v = __ldg(W1 + k * D + i) * __ldg(W1 + k * D + j);
        __half h, l;
        split_f16(v, h, l);
        g_PBh[(size_t)n * KP + k] = h;
        g_PBl[(size_t)n * KP + k] = l;
    } else {
        int nn = n - N_SYM;     // 0..127
        float v = (nn < D && k < D) ? W1[k * D + nn] : 0.0f;
        __half h, l;
        split_f16(v, h, l);
        g_BJh[nn * KP + k] = h;
        g_BJl[nn * KP + k] = l;
    }
}

// ---------------- HMMA GEMM: 96x64 CTA tile, 4 warps (2m x 2n), fp16 2-term ----------------
// blockIdx.x < NPAIRS: hess pair tile; else jac n-tile (bx - NPAIRS)
#define PITCH 240                          // bytes per smem row (112 fp16 + pad)
#define CHUNKS 14
#define A_TILE_BYTES (MTILE * PITCH)       // 23040
#define B_TILE_BYTES (NTILE * PITCH)       // 15360
#define SMEM_BYTES (A_TILE_BYTES + 2 * B_TILE_BYTES)  // 53760 -> 4 CTAs/SM
#define CPITCH 68                          // C staging pitch (floats)

template <int ROWS>
__device__ __forceinline__ void load_tile_async(uint32_t dst, const __half* __restrict__ src,
                                                int row0, int tid) {
    constexpr int TOT = ROWS * CHUNKS;
    #pragma unroll
    for (int it = 0; it < (TOT + THREADS - 1) / THREADS; it++) {
        int c = tid + it * THREADS;
        if (TOT % THREADS != 0 && c >= TOT) break;
        int row = c / CHUNKS, col = c % CHUNKS;
        cp16(dst + row * PITCH + col * 16,
             src + (size_t)(row0 + row) * KP + col * 8);
    }
}

__global__ void __launch_bounds__(THREADS, 4)
mma_gemm_kernel(float* __restrict__ Chess, float* __restrict__ Cjac) {
    int bx = blockIdx.x;
    bool is_jac = bx >= NPAIRS;

    const __half* __restrict__ Ah = is_jac ? g_AJh : g_AHh;
    const __half* __restrict__ Bh = is_jac ? g_BJh : g_PBh;
    const __half* __restrict__ Bl = is_jac ? g_BJl : g_PBl;
    int n0 = is_jac ? (bx - NPAIRS) * NTILE : bx * NTILE;

    extern __shared__ char smem[];
    uint32_t uAh = smem_to_u32(smem);
    uint32_t uBh = uAh + A_TILE_BYTES;
    uint32_t uBl = uBh + B_TILE_BYTES;

    int tid = threadIdx.x;
    int m0 = blockIdx.y * MTILE;

    load_tile_async<MTILE>(uAh, Ah, m0, tid);
    load_tile_async<NTILE>(uBh, Bh, n0, tid);
    load_tile_async<NTILE>(uBl, Bl, n0, tid);
    asm volatile("cp.async.commit_group;" ::: "memory");
    asm volatile("cp.async.wait_group 0;" ::: "memory");
    __syncthreads();

    int lane = tid & 31, wid = tid >> 5;
    int wm = (wid & 1) * 48;      // 2 m-warps x 48
    int wn = (wid >> 1) * 32;     // 2 n-warps x 32
    int t = lane >> 3, r = lane & 7;

    uint32_t aoff = (uint32_t)((wm + (t & 1) * 8 + r) * PITCH + (t >> 1) * 16);
    uint32_t boff = (uint32_t)((wn + (t >> 1) * 8 + r) * PITCH + (t & 1) * 16);

    float acc[3][4][4];
    #pragma unroll
    for (int i = 0; i < 3; i++)
        #pragma unroll
        for (int j = 0; j < 4; j++)
            #pragma unroll
            for (int e = 0; e < 4; e++) acc[i][j][e] = 0.0f;

    #pragma unroll
    for (int ks = 0; ks < K_STEPS; ks++) {
        uint32_t kb = ks * 32;
        uint32_t ah[3][4], bh[8], bl[8];
        #pragma unroll
        for (int mf = 0; mf < 3; mf++) ldm4(ah[mf], uAh + aoff + mf * 16 * PITCH + kb);
        ldm4(bh,     uBh + boff + kb);
        ldm4(bh + 4, uBh + boff + 16 * PITCH + kb);
        #pragma unroll
        for (int mf = 0; mf < 3; mf++)
            #pragma unroll
            for (int nf = 0; nf < 4; nf++)
                mma_f16(acc[mf][nf], ah[mf], bh[nf * 2], bh[nf * 2 + 1]);

        ldm4(bl,     uBl + boff + kb);
        ldm4(bl + 4, uBl + boff + 16 * PITCH + kb);
        #pragma unroll
        for (int mf = 0; mf < 3; mf++)
            #pragma unroll
            for (int nf = 0; nf < 4; nf++)
                mma_f16(acc[mf][nf], ah[mf], bl[nf * 2], bl[nf * 2 + 1]);
    }

    // ---- stage C tile in smem (96*68*4 = 26112 <= 53760) ----
    __syncthreads();
    float* Cs = reinterpret_cast<float*>(smem);
    #pragma unroll
    for (int mf = 0; mf < 3; mf++) {
        int mrow = wm + mf * 16 + (lane >> 2);
        #pragma unroll
        for (int nf = 0; nf < 4; nf++) {
            int ncol = wn + nf * 8 + 2 * (lane & 3);
            *reinterpret_cast<float2*>(&Cs[mrow * CPITCH + ncol]) =
                make_float2(acc[mf][nf][0], acc[mf][nf][1]);
            *reinterpret_cast<float2*>(&Cs[(mrow + 8) * CPITCH + ncol]) =
                make_float2(acc[mf][nf][2], acc[mf][nf][3]);
        }
    }
    __syncthreads();

    if (is_jac) {
        // jac: guarded scalar writes
        #pragma unroll
        for (int it = 0; it < MTILE * 64 / THREADS; it++) {
            int e = tid + it * THREADS;
            int m = e >> 6, nl = e & 63;
            int n = n0 + nl;
            int gm = m0 + m;
            if (n < D && gm < M_ROWS) Cjac[(size_t)gm * D + n] = Cs[m * CPITCH + nl];
        }
    } else {
        int bi, bj; decode_pair(bx, bi, bj);
        bool diag = (bi == bj);   // diagonal pair-tile: primary covers full block; skip mirror
        if (bi < 12 && bj < 12) {
            // fast path: float4 stores, only m-guard
            #pragma unroll
            for (int it = 0; it < MTILE * 16 / THREADS; it++) {
                int e = tid + it * THREADS;
                int m = e >> 4, q = e & 15;
                int gm = m0 + m;
                if (gm >= M_ROWS) continue;
                int i = bi * 8 + (q >> 1);
                int jb = bj * 8 + (q & 1) * 4;
                float4 v = *reinterpret_cast<const float4*>(&Cs[m * CPITCH + q * 4]);
                *reinterpret_cast<float4*>(&Chess[(size_t)gm * D2 + i * D + jb]) = v;
            }
            if (!diag) {
                #pragma unroll
                for (int it = 0; it < MTILE * 16 / THREADS; it++) {
                    int e = tid + it * THREADS;
                    int m = e >> 4, q = e & 15;
                    int gm = m0 + m;
                    if (gm >= M_ROWS) continue;
                    int lj = q >> 1, li4 = (q & 1) * 4;
                    int jrow = bj * 8 + lj;
                    int ib = bi * 8 + li4;
                    float4 v;
                    v.x = Cs[m * CPITCH + (li4 + 0) * 8 + lj];
                    v.y = Cs[m * CPITCH + (li4 + 1) * 8 + lj];
                    v.z = Cs[m * CPITCH + (li4 + 2) * 8 + lj];
                    v.w = Cs[m * CPITCH + (li4 + 3) * 8 + lj];
                    *reinterpret_cast<float4*>(&Chess[(size_t)gm * D2 + jrow * D + ib]) = v;
                }
            }
        } else {
            // edge tiles: scalar guarded
            #pragma unroll
            for (int it = 0; it < MTILE * 64 / THREADS; it++) {
                int e = tid + it * THREADS;
                int m = e >> 6, nl = e & 63;
                int gm = m0 + m;
                int i = bi * 8 + (nl >> 3), j = bj * 8 + (nl & 7);
                if (i < D && j < D && gm < M_ROWS)
                    Chess[(size_t)gm * D2 + i * D + j] = Cs[m * CPITCH + nl];
            }
            if (!diag) {
                #pragma unroll
                for (int it = 0; it < MTILE * 64 / THREADS; it++) {
                    int e = tid + it * THREADS;
                    int m = e >> 6, nl = e & 63;
                    int gm = m0 + m;
                    int lj = nl >> 3, li = nl & 7;
                    int i = bi * 8 + li, j = bj * 8 + lj;
                    if (i < D && j < D && gm < M_ROWS)
                        Chess[(size_t)gm * D2 + j * D + i] = Cs[m * CPITCH + li * 8 + lj];
                }
            }
        }
    }
}

// ---------------- host ----------------
extern "C" void kernel_launch(void* const* d_in, const int* in_sizes, int n_in,
                              void* d_out, int out_size) {
    const float* x  = (const float*)d_in[0];
    const float* W1 = (const float*)d_in[1];
    const float* b1 = (const float*)d_in[2];
    const float* W2 = (const float*)d_in[3];
    const float* b2 = (const float*)d_in[4];

    float* out  = (float*)d_out;
    float* jac  = out + Bsz * D;
    float* hess = jac + (size_t)Bsz * D * D;

    cudaFuncSetAttribute(mma_gemm_kernel, cudaFuncAttributeMaxDynamicSharedMemorySize, SMEM_BYTES);

    buildPBJ_kernel<<<N_SYM + NJ_PAD, 128>>>(W1);                          // 0
    fused_prep_kernel<<<Bsz + 1, 128>>>(x, W1, b1, W2, b2, out);           // 1
    {
        dim3 grid(NPAIRS + 2, M_PAD / MTILE);
        mma_gemm_kernel<<<grid, THREADS, SMEM_BYTES>>>(hess, jac);         // 2
    }
}